// round 12
// baseline (speedup 1.0000x reference)
#include <cuda_runtime.h>
#include <cuda_fp16.h>
#include <cstdint>

#define RV_NUM 10
#define RV_LEN 128
#define BZ     32
#define NREV   (BZ * RV_NUM)      // 320 reviews
#define ROWS   (NREV * RV_LEN)    // 40960 tokens per tensor
#define KD     300                // in_feat
#define KPAD   320                // padded K (multiple of 32)
#define ND     128                // out_feat / hdim
#define MTOK   (RV_NUM * RV_LEN)  // 1280 tokens per sample

// Scratch (no runtime allocs): transformed features, mean accumulators, W fp16.
__device__ float g_t[2][ROWS * ND];       // ta / tb (~42 MB, L2-resident)
__device__ float g_mean[2][BZ * ND];      // SUM of transformed feats (atomics)
__device__ __half g_wt_hi[ND * KPAD];     // W^T rounded to fp16  [n][k]

// ---------------------------------------------------------------------------
// PTX helpers (sm_103 base target: NO tcgen05; mma.sync / ldmatrix / cp.async)
// ---------------------------------------------------------------------------
__device__ __forceinline__ uint32_t smem_u32(const void* p) {
    uint32_t a;
    asm("{ .reg .u64 t; cvta.to.shared.u64 t, %1; cvt.u32.u64 %0, t; }"
        : "=r"(a) : "l"(p));
    return a;
}
__device__ __forceinline__ void cp_async16(uint32_t dst, const void* src) {
    asm volatile("cp.async.cg.shared.global [%0], [%1], 16;"
                 :: "r"(dst), "l"(src) : "memory");
}
__device__ __forceinline__ void cp_commit() {
    asm volatile("cp.async.commit_group;" ::: "memory");
}
__device__ __forceinline__ void cp_wait0() {
    asm volatile("cp.async.wait_group 0;" ::: "memory");
}
__device__ __forceinline__ void ldmx4(uint32_t addr, uint32_t r[4]) {
    asm volatile("ldmatrix.sync.aligned.m8n8.x4.shared.b16 {%0,%1,%2,%3}, [%4];"
                 : "=r"(r[0]), "=r"(r[1]), "=r"(r[2]), "=r"(r[3]) : "r"(addr));
}
__device__ __forceinline__ void mma16816(float d[4], const uint32_t a[4],
                                         uint32_t b0, uint32_t b1) {
    asm volatile(
        "mma.sync.aligned.m16n8k16.row.col.f32.f16.f16.f32 "
        "{%0,%1,%2,%3}, {%4,%5,%6,%7}, {%8,%9}, {%0,%1,%2,%3};"
        : "+f"(d[0]), "+f"(d[1]), "+f"(d[2]), "+f"(d[3])
        : "r"(a[0]), "r"(a[1]), "r"(a[2]), "r"(a[3]), "r"(b0), "r"(b1));
}

// ---------------------------------------------------------------------------
// Kernel 0: transpose W [300,128] f32 -> fp16 [128,320]; zero g_mean.
// ---------------------------------------------------------------------------
__global__ __launch_bounds__(256) void prep_w_kernel(const float* __restrict__ W)
{
    int gid = blockIdx.x * 256 + threadIdx.x;   // 160 * 256 = 40960
    if (gid < 2 * BZ * ND) ((float*)g_mean)[gid] = 0.f;
    int n = gid / KPAD, k = gid % KPAD;
    float v = (k < KD) ? W[k * ND + n] : 0.f;
    g_wt_hi[gid] = __float2half_rn(v);
}

// ---------------------------------------------------------------------------
// Kernel 1: HMMA GEMM  T = relu(X @ W + b), fp16 2-pass (A split hi/lo), fp32
// accum. M-tile 64: grid (640, 2), 256 threads, 8 warps as 2(m) x 4(n),
// warp tile 32x32. __launch_bounds__(256,4): 4 CTAs/SM = 32 warps/SM (full).
// Epilogue: bias+ReLU + fused mean atomics.
// ---------------------------------------------------------------------------
#define BM 64
#define BK 32
#define NCHUNK (KPAD / BK)            // 10
#define RS 40                         // fp16/row (80B rows: LDSM conflict-free)
#define AHI_OFF 0
#define ALO_OFF (BM * RS * 2)         // 5120
#define BHI_OFF (2 * BM * RS * 2)     // 10240
#define STAGE_BYTES (BHI_OFF + 128 * RS * 2)  // 20480
#define GEMM_SMEM (2 * STAGE_BYTES)   // 40960

// Per (p): 4 hi-MMAs then 4 lo-MMAs -> same-accumulator reuse distance 4.
__device__ __forceinline__ void compute_stage(
    uint32_t stgc, int wm, int wn, int lrow, int lk, float acc[2][4][4])
{
    #pragma unroll
    for (int ks = 0; ks < 2; ++ks) {
        uint32_t ah[2][4], al[2][4];
        #pragma unroll
        for (int mf = 0; mf < 2; ++mf) {
            uint32_t ad = stgc + AHI_OFF
                        + ((uint32_t)(wm * 32 + mf * 16 + lrow) * RS + ks * 16 + lk) * 2;
            ldmx4(ad, ah[mf]);
            ldmx4(ad + (ALO_OFF - AHI_OFF), al[mf]);
        }
        #pragma unroll
        for (int p = 0; p < 2; ++p) {
            uint32_t bd = stgc + BHI_OFF
                        + ((uint32_t)(wn * 32 + p * 16 + lrow) * RS + ks * 16 + lk) * 2;
            uint32_t rh[4];
            ldmx4(bd, rh);
            #pragma unroll
            for (int j = 0; j < 2; ++j)
                #pragma unroll
                for (int mf = 0; mf < 2; ++mf)
                    mma16816(acc[mf][2 * p + j], ah[mf], rh[j], rh[j + 2]);
            #pragma unroll
            for (int j = 0; j < 2; ++j)
                #pragma unroll
                for (int mf = 0; mf < 2; ++mf)
                    mma16816(acc[mf][2 * p + j], al[mf], rh[j], rh[j + 2]);
        }
    }
}

__global__ __launch_bounds__(256, 4) void gemm_mma_kernel(
    const float* __restrict__ A0, const float* __restrict__ A1,
    const float* __restrict__ bias)
{
    extern __shared__ char smem[];
    const uint32_t sb = smem_u32(smem);
    const int tid = threadIdx.x, wid = tid >> 5, lid = tid & 31;
    const int side = blockIdx.y;
    const int rowBase = blockIdx.x * BM;
    const float* __restrict__ A = side ? A1 : A0;

    const int wm = wid >> 2, wn = wid & 3;       // warp grid 2 x 4
    const int g = lid >> 3, lr = lid & 7;
    const int lrow = (g & 1) * 8 + lr;           // ldmatrix row within 16-frag
    const int lk   = (g >> 1) * 8;               // ldmatrix k offset within 16

    float acc[2][4][4];
    #pragma unroll
    for (int i = 0; i < 2; ++i)
        #pragma unroll
        for (int j = 0; j < 4; ++j)
            #pragma unroll
            for (int q = 0; q < 4; ++q) acc[i][j][q] = 0.f;

    // A loader: thread covers row=tid/4 (0..63), k-quarter=tid%4 (8 floats)
    const int arow = tid >> 2, aq = tid & 3;
    const float* agp = A + (size_t)(rowBase + arow) * KD + aq * 8;
    // B loader: thread covers row=tid/2 (0..127), k-half=tid%2 (16 halfs)
    const int bn = tid >> 1, bq = tid & 1;
    const __half* bgp = g_wt_hi + (size_t)bn * KPAD + bq * 16;
    const uint32_t bdst0 = sb + BHI_OFF + (uint32_t)bn * RS * 2 + bq * 32;

    float4 ap0, ap1;

    for (int c = 0; c < NCHUNK; ++c) {
        const int k0 = c * BK;
        const uint32_t stg_off = (uint32_t)(c & 1) * STAGE_BYTES;

        const int kb = k0 + aq * 8;
        ap0 = (kb < KD)     ? *(const float4*)(agp + k0)
                            : make_float4(0.f, 0.f, 0.f, 0.f);
        ap1 = (kb + 4 < KD) ? *(const float4*)(agp + k0 + 4)
                            : make_float4(0.f, 0.f, 0.f, 0.f);

        cp_async16(bdst0 + stg_off,      bgp + k0);
        cp_async16(bdst0 + stg_off + 16, bgp + k0 + 8);
        cp_commit();

        if (c > 0) compute_stage(sb + (uint32_t)((c - 1) & 1) * STAGE_BYTES,
                                 wm, wn, lrow, lk, acc);

        {
            const uint32_t off = stg_off + AHI_OFF
                               + ((uint32_t)arow * RS + aq * 8) * 2;
            __half2 h01 = __floats2half2_rn(ap0.x, ap0.y);
            __half2 h23 = __floats2half2_rn(ap0.z, ap0.w);
            __half2 h45 = __floats2half2_rn(ap1.x, ap1.y);
            __half2 h67 = __floats2half2_rn(ap1.z, ap1.w);
            __half2 l01 = __floats2half2_rn(ap0.x - __low2float(h01),
                                            ap0.y - __high2float(h01));
            __half2 l23 = __floats2half2_rn(ap0.z - __low2float(h23),
                                            ap0.w - __high2float(h23));
            __half2 l45 = __floats2half2_rn(ap1.x - __low2float(h45),
                                            ap1.y - __high2float(h45));
            __half2 l67 = __floats2half2_rn(ap1.z - __low2float(h67),
                                            ap1.w - __high2float(h67));
            *(uint4*)(smem + off) = make_uint4(
                *(uint32_t*)&h01, *(uint32_t*)&h23,
                *(uint32_t*)&h45, *(uint32_t*)&h67);
            *(uint4*)(smem + off + (ALO_OFF - AHI_OFF)) = make_uint4(
                *(uint32_t*)&l01, *(uint32_t*)&l23,
                *(uint32_t*)&l45, *(uint32_t*)&l67);
        }
        cp_wait0();
        __syncthreads();
    }
    compute_stage(sb + (uint32_t)((NCHUNK - 1) & 1) * STAGE_BYTES,
                  wm, wn, lrow, lk, acc);

    // Epilogue: bias + ReLU -> global; column sums -> g_mean (fused mean)
    const int trow = lid >> 2, tcol = (lid & 3) * 2;
    float bcol[4][2];
    #pragma unroll
    for (int nf = 0; nf < 4; ++nf) {
        bcol[nf][0] = __ldg(bias + wn * 32 + nf * 8 + tcol);
        bcol[nf][1] = __ldg(bias + wn * 32 + nf * 8 + tcol + 1);
    }
    float cs[4][2];
    #pragma unroll
    for (int nf = 0; nf < 4; ++nf) { cs[nf][0] = 0.f; cs[nf][1] = 0.f; }

    float* Cb = g_t[side];
    #pragma unroll
    for (int mf = 0; mf < 2; ++mf) {
        const int r0 = rowBase + wm * 32 + mf * 16 + trow;
        #pragma unroll
        for (int nf = 0; nf < 4; ++nf) {
            const int c0 = wn * 32 + nf * 8 + tcol;
            float2 v0, v1;
            v0.x = fmaxf(acc[mf][nf][0] + bcol[nf][0], 0.f);
            v0.y = fmaxf(acc[mf][nf][1] + bcol[nf][1], 0.f);
            v1.x = fmaxf(acc[mf][nf][2] + bcol[nf][0], 0.f);
            v1.y = fmaxf(acc[mf][nf][3] + bcol[nf][1], 0.f);
            *(float2*)(Cb + (size_t)r0 * ND + c0)       = v0;
            *(float2*)(Cb + (size_t)(r0 + 8) * ND + c0) = v1;
            cs[nf][0] += v0.x + v1.x;
            cs[nf][1] += v0.y + v1.y;
        }
    }
    #pragma unroll
    for (int o = 4; o <= 16; o <<= 1)
        #pragma unroll
        for (int nf = 0; nf < 4; ++nf) {
            cs[nf][0] += __shfl_xor_sync(0xffffffffu, cs[nf][0], o);
            cs[nf][1] += __shfl_xor_sync(0xffffffffu, cs[nf][1], o);
        }
    if (lid < 4) {
        const int b = blockIdx.x / (MTOK / BM);   // 20 M-tiles per sample
        float* mptr = g_mean[side] + b * ND + wn * 32;
        #pragma unroll
        for (int nf = 0; nf < 4; ++nf) {
            atomicAdd(mptr + nf * 8 + tcol,     cs[nf][0]);
            atomicAdd(mptr + nf * 8 + tcol + 1, cs[nf][1]);
        }
    }
}

// ---------------------------------------------------------------------------
// Kernel 2: attention per review — two coalesced float4 passes over g_t.
// Grid (320, 2), 128 threads.
// ---------------------------------------------------------------------------
__global__ __launch_bounds__(128) void attn_kernel(
    const int* __restrict__ mask_a, const int* __restrict__ mask_b,
    float* __restrict__ out)
{
    __shared__ __align__(16) float meanv[128];
    __shared__ __align__(16) float part[4][128];
    __shared__ float sc[128], wv[128], red[8];

    const int side = blockIdx.y;
    const int n    = blockIdx.x;
    const int b    = n / RV_NUM;
    const int tid  = threadIdx.x;
    const int lane = tid & 31, w = tid >> 5;

    const float* __restrict__ T = g_t[side] + (size_t)n * RV_LEN * ND;
    const int*   __restrict__ mask = side ? mask_b : mask_a;

    meanv[tid] = g_mean[side ^ 1][b * ND + tid] * (1.0f / (float)MTOK);
    __syncthreads();

    const float4 mv = *(const float4*)&meanv[lane * 4];

    // Pass 1: scores. Warp w covers tokens [w*32, w*32+32); lanes split the row.
    #pragma unroll 8
    for (int t = 0; t < 32; ++t) {
        const int l = w * 32 + t;
        float4 x = *(const float4*)(T + (size_t)l * ND + lane * 4);
        float p = x.x * mv.x + x.y * mv.y + x.z * mv.z + x.w * mv.w;
        #pragma unroll
        for (int o = 16; o; o >>= 1) p += __shfl_xor_sync(0xffffffffu, p, o);
        if (lane == 0) sc[l] = p;
    }
    __syncthreads();

    // Masked softmax over this review's 128 tokens (thread = token).
    float logit = (mask[n * RV_LEN + tid] > 0) ? sc[tid] : -1e9f;
    float v = logit;
    #pragma unroll
    for (int o = 16; o; o >>= 1) v = fmaxf(v, __shfl_xor_sync(0xffffffffu, v, o));
    if (lane == 0) red[w] = v;
    __syncthreads();
    const float gmax = fmaxf(fmaxf(red[0], red[1]), fmaxf(red[2], red[3]));

    const float e = __expf(logit - gmax);
    v = e;
    #pragma unroll
    for (int o = 16; o; o >>= 1) v += __shfl_xor_sync(0xffffffffu, v, o);
    if (lane == 0) red[4 + w] = v;
    __syncthreads();
    const float gsum = red[4] + red[5] + red[6] + red[7];

    const float wgt = e / gsum;
    wv[tid] = wgt;
    out[(size_t)(2 + side) * ROWS + (size_t)n * RV_LEN + tid] = wgt;
    __syncthreads();

    // Pass 2: weighted sum. Row-group w handles rows l ≡ w (mod 4), lanes split d.
    float4 acc = make_float4(0.f, 0.f, 0.f, 0.f);
    #pragma unroll 8
    for (int l = w; l < RV_LEN; l += 4) {
        float4 x = *(const float4*)(T + (size_t)l * ND + lane * 4);
        const float wl = wv[l];
        acc.x += wl * x.x; acc.y += wl * x.y;
        acc.z += wl * x.z; acc.w += wl * x.w;
    }
    *(float4*)&part[w][lane * 4] = acc;
    __syncthreads();
    float s = part[0][tid] + part[1][tid] + part[2][tid] + part[3][tid];
    out[(size_t)side * ROWS + (size_t)n * ND + tid] = s;
}

// ---------------------------------------------------------------------------
extern "C" void kernel_launch(void* const* d_in, const int* in_sizes, int n_in,
                              void* d_out, int out_size)
{
    const float* seq_a  = (const float*)d_in[0];
    const float* seq_b  = (const float*)d_in[1];
    const int*   mask_a = (const int*)d_in[2];
    const int*   mask_b = (const int*)d_in[3];
    const float* W      = (const float*)d_in[4];
    const float* bias   = (const float*)d_in[5];
    float* out = (float*)d_out;

    cudaFuncSetAttribute(gemm_mma_kernel, cudaFuncAttributeMaxDynamicSharedMemorySize, GEMM_SMEM);

    prep_w_kernel<<<160, 256>>>(W);

    dim3 g1(ROWS / BM, 2);
    gemm_mma_kernel<<<g1, 256, GEMM_SMEM>>>(seq_a, seq_b, bias);

    dim3 g3(NREV, 2);
    attn_kernel<<<g3, 128>>>(mask_a, mask_b, out);
}

// round 14
// speedup vs baseline: 1.0827x; 1.0827x over previous
#include <cuda_runtime.h>
#include <cuda_fp16.h>
#include <cstdint>

#define RV_NUM 10
#define RV_LEN 128
#define BZ     32
#define NREV   (BZ * RV_NUM)      // 320 reviews
#define ROWS   (NREV * RV_LEN)    // 40960 tokens per tensor
#define KD     300                // in_feat
#define KPAD   320                // padded K (multiple of 32)
#define ND     128                // out_feat / hdim
#define MTOK   (RV_NUM * RV_LEN)  // 1280 tokens per sample

// Scratch (no runtime allocs): transformed features, mean accumulators, W fp16.
__device__ float g_t[2][ROWS * ND];       // ta / tb (~42 MB, L2-resident)
__device__ float g_mean[2][BZ * ND];      // SUM of transformed feats (atomics)
__device__ __half g_wt_hi[ND * KPAD];     // W^T rounded to fp16  [n][k]

// ---------------------------------------------------------------------------
// PTX helpers (sm_103 base target: NO tcgen05; mma.sync / ldmatrix / cp.async)
// ---------------------------------------------------------------------------
__device__ __forceinline__ uint32_t smem_u32(const void* p) {
    uint32_t a;
    asm("{ .reg .u64 t; cvta.to.shared.u64 t, %1; cvt.u32.u64 %0, t; }"
        : "=r"(a) : "l"(p));
    return a;
}
__device__ __forceinline__ void cp_async16(uint32_t dst, const void* src) {
    asm volatile("cp.async.cg.shared.global [%0], [%1], 16;"
                 :: "r"(dst), "l"(src) : "memory");
}
// 16B copy with src-size zfill (bytes beyond src_bytes are zero-filled).
__device__ __forceinline__ void cp_async16_zfill(uint32_t dst, const void* src,
                                                 uint32_t src_bytes) {
    asm volatile("cp.async.cg.shared.global [%0], [%1], 16, %2;"
                 :: "r"(dst), "l"(src), "r"(src_bytes) : "memory");
}
__device__ __forceinline__ void cp_commit() {
    asm volatile("cp.async.commit_group;" ::: "memory");
}
__device__ __forceinline__ void cp_wait0() {
    asm volatile("cp.async.wait_group 0;" ::: "memory");
}
__device__ __forceinline__ void ldmx4(uint32_t addr, uint32_t r[4]) {
    asm volatile("ldmatrix.sync.aligned.m8n8.x4.shared.b16 {%0,%1,%2,%3}, [%4];"
                 : "=r"(r[0]), "=r"(r[1]), "=r"(r[2]), "=r"(r[3]) : "r"(addr));
}
__device__ __forceinline__ void mma16816(float d[4], const uint32_t a[4],
                                         uint32_t b0, uint32_t b1) {
    asm volatile(
        "mma.sync.aligned.m16n8k16.row.col.f32.f16.f16.f32 "
        "{%0,%1,%2,%3}, {%4,%5,%6,%7}, {%8,%9}, {%0,%1,%2,%3};"
        : "+f"(d[0]), "+f"(d[1]), "+f"(d[2]), "+f"(d[3])
        : "r"(a[0]), "r"(a[1]), "r"(a[2]), "r"(a[3]), "r"(b0), "r"(b1));
}

// ---------------------------------------------------------------------------
// Kernel 0: transpose W [300,128] f32 -> fp16 [128,320]; zero g_mean.
// ---------------------------------------------------------------------------
__global__ __launch_bounds__(256) void prep_w_kernel(const float* __restrict__ W)
{
    int gid = blockIdx.x * 256 + threadIdx.x;   // 160 * 256 = 40960
    if (gid < 2 * BZ * ND) ((float*)g_mean)[gid] = 0.f;
    int n = gid / KPAD, k = gid % KPAD;
    float v = (k < KD) ? W[k * ND + n] : 0.f;
    g_wt_hi[gid] = __float2half_rn(v);
}

// ---------------------------------------------------------------------------
// Kernel 1: HMMA GEMM  T = relu(X @ W + b), fp16 2-pass (A split hi/lo), fp32
// accum. M-tile 64: grid (640, 2), 256 threads, 8 warps as 2(m) x 4(n),
// warp tile 32x32. A is cp.async'd as fp32 into smem staging and converted
// smem->smem (no register prefetch) -> mainloop live regs ~56, so
// __launch_bounds__(256,4) = 32 warps/SM fits WITHOUT spills.
// Epilogue: bias+ReLU + fused mean atomics.
// ---------------------------------------------------------------------------
#define BM 64
#define BK 32
#define NCHUNK (KPAD / BK)            // 10
#define RS 40                         // fp16/row (80B rows: LDSM conflict-free)
#define AHI_OFF 0
#define ALO_OFF (BM * RS * 2)         // 5120
#define BHI_OFF (2 * BM * RS * 2)     // 10240
#define STAGE_BYTES (BHI_OFF + 128 * RS * 2)  // 20480
#define AF32_OFF (2 * STAGE_BYTES)    // 40960: fp32 A staging (single buffer)
#define AF32_RSTRIDE 36               // floats per staged row (144B, pad: no LDS conflicts)
#define GEMM_SMEM (AF32_OFF + BM * AF32_RSTRIDE * 4)  // 40960 + 9216 = 50176

// Low-liveness schedule: full hi pass (A-hi in 8 regs), then reload same regs
// with A-lo for the lo pass. Same-acc reuse distance = 8 MMAs.
__device__ __forceinline__ void compute_stage(
    uint32_t stgc, int wm, int wn, int lrow, int lk, float acc[2][4][4])
{
    #pragma unroll
    for (int ks = 0; ks < 2; ++ks) {
        const uint32_t abase = stgc
            + ((uint32_t)(wm * 32 + lrow) * RS + ks * 16 + lk) * 2;
        const uint32_t bbase = stgc + BHI_OFF
            + ((uint32_t)(wn * 32 + lrow) * RS + ks * 16 + lk) * 2;
        #pragma unroll
        for (int half = 0; half < 2; ++half) {   // 0 = A-hi, 1 = A-lo
            uint32_t a0[4], a1[4];
            const uint32_t ao = abase + (half ? (ALO_OFF - AHI_OFF) : 0u);
            ldmx4(ao, a0);
            ldmx4(ao + 16u * RS * 2u, a1);
            #pragma unroll
            for (int p = 0; p < 2; ++p) {
                uint32_t rh[4];
                ldmx4(bbase + (uint32_t)(p * 16) * RS * 2u, rh);
                #pragma unroll
                for (int j = 0; j < 2; ++j) {
                    mma16816(acc[0][2 * p + j], a0, rh[j], rh[j + 2]);
                    mma16816(acc[1][2 * p + j], a1, rh[j], rh[j + 2]);
                }
            }
        }
    }
}

__global__ __launch_bounds__(256, 4) void gemm_mma_kernel(
    const float* __restrict__ A0, const float* __restrict__ A1,
    const float* __restrict__ bias)
{
    extern __shared__ char smem[];
    const uint32_t sb = smem_u32(smem);
    const int tid = threadIdx.x, wid = tid >> 5, lid = tid & 31;
    const int side = blockIdx.y;
    const int rowBase = blockIdx.x * BM;
    const float* __restrict__ A = side ? A1 : A0;

    const int wm = wid >> 2, wn = wid & 3;       // warp grid 2 x 4
    const int g = lid >> 3, lr = lid & 7;
    const int lrow = (g & 1) * 8 + lr;           // ldmatrix row within 16-frag
    const int lk   = (g >> 1) * 8;               // ldmatrix k offset within 16

    float acc[2][4][4];
    #pragma unroll
    for (int i = 0; i < 2; ++i)
        #pragma unroll
        for (int j = 0; j < 4; ++j)
            #pragma unroll
            for (int q = 0; q < 4; ++q) acc[i][j][q] = 0.f;

    // A fp32 loader: 512 x 16B per chunk; thread does i = tid and tid+256.
    //   i -> row = i>>3, quad q = i&7 (16B = 4 floats at k0 + q*4)
    // B loader: thread covers row=tid/2 (0..127), k-half=tid%2 (16 halfs)
    const int bn = tid >> 1, bq = tid & 1;
    const __half* bgp = g_wt_hi + (size_t)bn * KPAD + bq * 16;
    const uint32_t bdst0 = sb + BHI_OFF + (uint32_t)bn * RS * 2 + bq * 32;
    // convert mapping: row = tid>>2, 8 floats at (tid&3)*8
    const int crow = tid >> 2, cq = tid & 3;

    for (int c = 0; c < NCHUNK; ++c) {
        const int k0 = c * BK;
        const uint32_t stg_off = (uint32_t)(c & 1) * STAGE_BYTES;

        // A fp32 -> smem staging (zfill beyond KD)
        #pragma unroll
        for (int h = 0; h < 2; ++h) {
            const int i = tid + h * 256;
            const int row = i >> 3, q = i & 7;
            const int kidx = k0 + q * 4;
            int sbytes = (KD - kidx) * 4;
            sbytes = sbytes < 0 ? 0 : (sbytes > 16 ? 16 : sbytes);
            cp_async16_zfill(sb + AF32_OFF + (uint32_t)(row * AF32_RSTRIDE + q * 4) * 4,
                             A + (size_t)(rowBase + row) * KD + kidx,
                             (uint32_t)sbytes);
        }
        // B fp16 -> stage
        cp_async16(bdst0 + stg_off,      bgp + k0);
        cp_async16(bdst0 + stg_off + 16, bgp + k0 + 8);
        cp_commit();

        if (c > 0) compute_stage(sb + (uint32_t)((c - 1) & 1) * STAGE_BYTES,
                                 wm, wn, lrow, lk, acc);

        cp_wait0();
        __syncthreads();

        // Convert staged fp32 -> hi/lo fp16 into stage[c&1]
        {
            const float* src = (const float*)(smem + AF32_OFF)
                             + crow * AF32_RSTRIDE + cq * 8;
            float4 v0 = *(const float4*)src;
            float4 v1 = *(const float4*)(src + 4);
            const uint32_t off = stg_off + AHI_OFF
                               + ((uint32_t)crow * RS + cq * 8) * 2;
            __half2 h01 = __floats2half2_rn(v0.x, v0.y);
            __half2 h23 = __floats2half2_rn(v0.z, v0.w);
            __half2 h45 = __floats2half2_rn(v1.x, v1.y);
            __half2 h67 = __floats2half2_rn(v1.z, v1.w);
            __half2 l01 = __floats2half2_rn(v0.x - __low2float(h01),
                                            v0.y - __high2float(h01));
            __half2 l23 = __floats2half2_rn(v0.z - __low2float(h23),
                                            v0.w - __high2float(h23));
            __half2 l45 = __floats2half2_rn(v1.x - __low2float(h45),
                                            v1.y - __high2float(h45));
            __half2 l67 = __floats2half2_rn(v1.z - __low2float(h67),
                                            v1.w - __high2float(h67));
            *(uint4*)(smem + off) = make_uint4(
                *(uint32_t*)&h01, *(uint32_t*)&h23,
                *(uint32_t*)&h45, *(uint32_t*)&h67);
            *(uint4*)(smem + off + (ALO_OFF - AHI_OFF)) = make_uint4(
                *(uint32_t*)&l01, *(uint32_t*)&l23,
                *(uint32_t*)&l45, *(uint32_t*)&l67);
        }
        __syncthreads();   // stage ready; fp32 staging free for next chunk
    }
    compute_stage(sb + (uint32_t)((NCHUNK - 1) & 1) * STAGE_BYTES,
                  wm, wn, lrow, lk, acc);

    // Epilogue: bias + ReLU -> global; column sums -> g_mean (fused mean)
    const int trow = lid >> 2, tcol = (lid & 3) * 2;
    float bcol[4][2];
    #pragma unroll
    for (int nf = 0; nf < 4; ++nf) {
        bcol[nf][0] = __ldg(bias + wn * 32 + nf * 8 + tcol);
        bcol[nf][1] = __ldg(bias + wn * 32 + nf * 8 + tcol + 1);
    }
    float cs[4][2];
    #pragma unroll
    for (int nf = 0; nf < 4; ++nf) { cs[nf][0] = 0.f; cs[nf][1] = 0.f; }

    float* Cb = g_t[side];
    #pragma unroll
    for (int mf = 0; mf < 2; ++mf) {
        const int r0 = rowBase + wm * 32 + mf * 16 + trow;
        #pragma unroll
        for (int nf = 0; nf < 4; ++nf) {
            const int c0 = wn * 32 + nf * 8 + tcol;
            float2 v0, v1;
            v0.x = fmaxf(acc[mf][nf][0] + bcol[nf][0], 0.f);
            v0.y = fmaxf(acc[mf][nf][1] + bcol[nf][1], 0.f);
            v1.x = fmaxf(acc[mf][nf][2] + bcol[nf][0], 0.f);
            v1.y = fmaxf(acc[mf][nf][3] + bcol[nf][1], 0.f);
            *(float2*)(Cb + (size_t)r0 * ND + c0)       = v0;
            *(float2*)(Cb + (size_t)(r0 + 8) * ND + c0) = v1;
            cs[nf][0] += v0.x + v1.x;
            cs[nf][1] += v0.y + v1.y;
        }
    }
    #pragma unroll
    for (int o = 4; o <= 16; o <<= 1)
        #pragma unroll
        for (int nf = 0; nf < 4; ++nf) {
            cs[nf][0] += __shfl_xor_sync(0xffffffffu, cs[nf][0], o);
            cs[nf][1] += __shfl_xor_sync(0xffffffffu, cs[nf][1], o);
        }
    if (lid < 4) {
        const int b = blockIdx.x / (MTOK / BM);   // 20 M-tiles per sample
        float* mptr = g_mean[side] + b * ND + wn * 32;
        #pragma unroll
        for (int nf = 0; nf < 4; ++nf) {
            atomicAdd(mptr + nf * 8 + tcol,     cs[nf][0]);
            atomicAdd(mptr + nf * 8 + tcol + 1, cs[nf][1]);
        }
    }
}

// ---------------------------------------------------------------------------
// Kernel 2: attention per review — two coalesced float4 passes over g_t.
// Grid (320, 2), 128 threads.
// ---------------------------------------------------------------------------
__global__ __launch_bounds__(128) void attn_kernel(
    const int* __restrict__ mask_a, const int* __restrict__ mask_b,
    float* __restrict__ out)
{
    __shared__ __align__(16) float meanv[128];
    __shared__ __align__(16) float part[4][128];
    __shared__ float sc[128], wv[128], red[8];

    const int side = blockIdx.y;
    const int n    = blockIdx.x;
    const int b    = n / RV_NUM;
    const int tid  = threadIdx.x;
    const int lane = tid & 31, w = tid >> 5;

    const float* __restrict__ T = g_t[side] + (size_t)n * RV_LEN * ND;
    const int*   __restrict__ mask = side ? mask_b : mask_a;

    meanv[tid] = g_mean[side ^ 1][b * ND + tid] * (1.0f / (float)MTOK);
    __syncthreads();

    const float4 mv = *(const float4*)&meanv[lane * 4];

    // Pass 1: scores. Warp w covers tokens [w*32, w*32+32); lanes split the row.
    #pragma unroll 8
    for (int t = 0; t < 32; ++t) {
        const int l = w * 32 + t;
        float4 x = *(const float4*)(T + (size_t)l * ND + lane * 4);
        float p = x.x * mv.x + x.y * mv.y + x.z * mv.z + x.w * mv.w;
        #pragma unroll
        for (int o = 16; o; o >>= 1) p += __shfl_xor_sync(0xffffffffu, p, o);
        if (lane == 0) sc[l] = p;
    }
    __syncthreads();

    // Masked softmax over this review's 128 tokens (thread = token).
    float logit = (mask[n * RV_LEN + tid] > 0) ? sc[tid] : -1e9f;
    float v = logit;
    #pragma unroll
    for (int o = 16; o; o >>= 1) v = fmaxf(v, __shfl_xor_sync(0xffffffffu, v, o));
    if (lane == 0) red[w] = v;
    __syncthreads();
    const float gmax = fmaxf(fmaxf(red[0], red[1]), fmaxf(red[2], red[3]));

    const float e = __expf(logit - gmax);
    v = e;
    #pragma unroll
    for (int o = 16; o; o >>= 1) v += __shfl_xor_sync(0xffffffffu, v, o);
    if (lane == 0) red[4 + w] = v;
    __syncthreads();
    const float gsum = red[4] + red[5] + red[6] + red[7];

    const float wgt = e / gsum;
    wv[tid] = wgt;
    out[(size_t)(2 + side) * ROWS + (size_t)n * RV_LEN + tid] = wgt;
    __syncthreads();

    // Pass 2: weighted sum. Row-group w handles rows l ≡ w (mod 4), lanes split d.
    float4 acc = make_float4(0.f, 0.f, 0.f, 0.f);
    #pragma unroll 8
    for (int l = w; l < RV_LEN; l += 4) {
        float4 x = *(const float4*)(T + (size_t)l * ND + lane * 4);
        const float wl = wv[l];
        acc.x += wl * x.x; acc.y += wl * x.y;
        acc.z += wl * x.z; acc.w += wl * x.w;
    }
    *(float4*)&part[w][lane * 4] = acc;
    __syncthreads();
    float s = part[0][tid] + part[1][tid] + part[2][tid] + part[3][tid];
    out[(size_t)side * ROWS + (size_t)n * ND + tid] = s;
}

// ---------------------------------------------------------------------------
extern "C" void kernel_launch(void* const* d_in, const int* in_sizes, int n_in,
                              void* d_out, int out_size)
{
    const float* seq_a  = (const float*)d_in[0];
    const float* seq_b  = (const float*)d_in[1];
    const int*   mask_a = (const int*)d_in[2];
    const int*   mask_b = (const int*)d_in[3];
    const float* W      = (const float*)d_in[4];
    const float* bias   = (const float*)d_in[5];
    float* out = (float*)d_out;

    cudaFuncSetAttribute(gemm_mma_kernel, cudaFuncAttributeMaxDynamicSharedMemorySize, GEMM_SMEM);

    prep_w_kernel<<<160, 256>>>(W);

    dim3 g1(ROWS / BM, 2);
    gemm_mma_kernel<<<g1, 256, GEMM_SMEM>>>(seq_a, seq_b, bias);

    dim3 g3(NREV, 2);
    attn_kernel<<<g3, 128>>>(mask_a, mask_b, out);
}

// round 15
// speedup vs baseline: 1.0860x; 1.0030x over previous
#include <cuda_runtime.h>
#include <cuda_fp16.h>
#include <cstdint>

#define RV_NUM 10
#define RV_LEN 128
#define BZ     32
#define NREV   (BZ * RV_NUM)      // 320 reviews
#define ROWS   (NREV * RV_LEN)    // 40960 tokens per tensor
#define KD     300                // in_feat
#define KPAD   320                // padded K (multiple of 32)
#define ND     128                // out_feat / hdim
#define MTOK   (RV_NUM * RV_LEN)  // 1280 tokens per sample

// Scratch (no runtime allocs): transformed features, mean accumulators, W fp16.
__device__ float g_t[2][ROWS * ND];       // ta / tb (~42 MB, L2-resident)
__device__ float g_mean[2][BZ * ND];      // SUM of transformed feats (atomics)
__device__ __half g_wt_hi[ND * KPAD];     // W^T rounded to fp16  [n][k]

// ---------------------------------------------------------------------------
// PTX helpers (sm_103 base target: NO tcgen05; mma.sync / ldmatrix / cp.async)
// ---------------------------------------------------------------------------
__device__ __forceinline__ uint32_t smem_u32(const void* p) {
    uint32_t a;
    asm("{ .reg .u64 t; cvta.to.shared.u64 t, %1; cvt.u32.u64 %0, t; }"
        : "=r"(a) : "l"(p));
    return a;
}
__device__ __forceinline__ void cp_async16(uint32_t dst, const void* src) {
    asm volatile("cp.async.cg.shared.global [%0], [%1], 16;"
                 :: "r"(dst), "l"(src) : "memory");
}
__device__ __forceinline__ void cp_commit() {
    asm volatile("cp.async.commit_group;" ::: "memory");
}
__device__ __forceinline__ void cp_wait0() {
    asm volatile("cp.async.wait_group 0;" ::: "memory");
}
__device__ __forceinline__ void ldmx4(uint32_t addr, uint32_t r[4]) {
    asm volatile("ldmatrix.sync.aligned.m8n8.x4.shared.b16 {%0,%1,%2,%3}, [%4];"
                 : "=r"(r[0]), "=r"(r[1]), "=r"(r[2]), "=r"(r[3]) : "r"(addr));
}
__device__ __forceinline__ void mma16816(float d[4], const uint32_t a[4],
                                         uint32_t b0, uint32_t b1) {
    asm volatile(
        "mma.sync.aligned.m16n8k16.row.col.f32.f16.f16.f32 "
        "{%0,%1,%2,%3}, {%4,%5,%6,%7}, {%8,%9}, {%0,%1,%2,%3};"
        : "+f"(d[0]), "+f"(d[1]), "+f"(d[2]), "+f"(d[3])
        : "r"(a[0]), "r"(a[1]), "r"(a[2]), "r"(a[3]), "r"(b0), "r"(b1));
}

// ---------------------------------------------------------------------------
// Kernel 0: transpose W [300,128] f32 -> fp16 [128,320]; zero g_mean.
// Read side fully coalesced (W[gid]); strided 2B stores are fire-and-forget.
// ---------------------------------------------------------------------------
__global__ __launch_bounds__(256) void prep_w_kernel(const float* __restrict__ W)
{
    int gid = blockIdx.x * 256 + threadIdx.x;   // 160 * 256 = 40960
    if (gid < 2 * BZ * ND) ((float*)g_mean)[gid] = 0.f;
    int k = gid >> 7;          // 0..319
    int n = gid & 127;
    float v = (k < KD) ? W[k * ND + n] : 0.f;   // == W[gid] when k < KD
    g_wt_hi[(size_t)n * KPAD + k] = __float2half_rn(v);
}

// ---------------------------------------------------------------------------
// Kernel 1: HMMA GEMM  T = relu(X @ W + b), fp16 2-pass (A split hi/lo), fp32
// accum. M-tile 64: grid (640, 2), 256 threads, 8 warps as 2(m) x 4(n),
// warp tile 32x32, __launch_bounds__(256,3): 3 CTAs/SM (proven optimum).
// K trimmed: chunks 0..8 full (k<288), chunk 9 runs 1 k-step (k 288..304;
// real data ends at 300, rest exact zeros). Epilogue: bias+ReLU + fused mean.
// ---------------------------------------------------------------------------
#define BM 64
#define BK 32
#define NCHUNK (KPAD / BK)            // 10
#define RS 40                         // fp16/row (80B rows: LDSM conflict-free)
#define AHI_OFF 0
#define ALO_OFF (BM * RS * 2)         // 5120
#define BHI_OFF (2 * BM * RS * 2)     // 10240
#define STAGE_BYTES (BHI_OFF + 128 * RS * 2)  // 20480
#define GEMM_SMEM (2 * STAGE_BYTES)   // 40960

// Per (p): 4 hi-MMAs then 4 lo-MMAs -> same-accumulator reuse distance 4.
template <int NKS>
__device__ __forceinline__ void compute_stage(
    uint32_t stgc, int wm, int wn, int lrow, int lk, float acc[2][4][4])
{
    #pragma unroll
    for (int ks = 0; ks < NKS; ++ks) {
        uint32_t ah[2][4], al[2][4];
        #pragma unroll
        for (int mf = 0; mf < 2; ++mf) {
            uint32_t ad = stgc + AHI_OFF
                        + ((uint32_t)(wm * 32 + mf * 16 + lrow) * RS + ks * 16 + lk) * 2;
            ldmx4(ad, ah[mf]);
            ldmx4(ad + (ALO_OFF - AHI_OFF), al[mf]);
        }
        #pragma unroll
        for (int p = 0; p < 2; ++p) {
            uint32_t bd = stgc + BHI_OFF
                        + ((uint32_t)(wn * 32 + p * 16 + lrow) * RS + ks * 16 + lk) * 2;
            uint32_t rh[4];
            ldmx4(bd, rh);
            #pragma unroll
            for (int j = 0; j < 2; ++j)
                #pragma unroll
                for (int mf = 0; mf < 2; ++mf)
                    mma16816(acc[mf][2 * p + j], ah[mf], rh[j], rh[j + 2]);
            #pragma unroll
            for (int j = 0; j < 2; ++j)
                #pragma unroll
                for (int mf = 0; mf < 2; ++mf)
                    mma16816(acc[mf][2 * p + j], al[mf], rh[j], rh[j + 2]);
        }
    }
}

__global__ __launch_bounds__(256, 3) void gemm_mma_kernel(
    const float* __restrict__ A0, const float* __restrict__ A1,
    const float* __restrict__ bias)
{
    extern __shared__ char smem[];
    const uint32_t sb = smem_u32(smem);
    const int tid = threadIdx.x, wid = tid >> 5, lid = tid & 31;
    const int side = blockIdx.y;
    const int rowBase = blockIdx.x * BM;
    const float* __restrict__ A = side ? A1 : A0;

    const int wm = wid >> 2, wn = wid & 3;       // warp grid 2 x 4
    const int g = lid >> 3, lr = lid & 7;
    const int lrow = (g & 1) * 8 + lr;           // ldmatrix row within 16-frag
    const int lk   = (g >> 1) * 8;               // ldmatrix k offset within 16

    float acc[2][4][4];
    #pragma unroll
    for (int i = 0; i < 2; ++i)
        #pragma unroll
        for (int j = 0; j < 4; ++j)
            #pragma unroll
            for (int q = 0; q < 4; ++q) acc[i][j][q] = 0.f;

    // A loader: thread covers row=tid/4 (0..63), k-quarter=tid%4 (8 floats)
    const int arow = tid >> 2, aq = tid & 3;
    const float* agp = A + (size_t)(rowBase + arow) * KD + aq * 8;
    // B loader: thread covers row=tid/2 (0..127), k-half=tid%2 (16 halfs)
    const int bn = tid >> 1, bq = tid & 1;
    const __half* bgp = g_wt_hi + (size_t)bn * KPAD + bq * 16;
    const uint32_t bdst0 = sb + BHI_OFF + (uint32_t)bn * RS * 2 + bq * 32;

    float4 ap0, ap1;

    for (int c = 0; c < NCHUNK; ++c) {
        const int k0 = c * BK;
        const uint32_t stg_off = (uint32_t)(c & 1) * STAGE_BYTES;

        const int kb = k0 + aq * 8;
        ap0 = (kb < KD)     ? *(const float4*)(agp + k0)
                            : make_float4(0.f, 0.f, 0.f, 0.f);
        ap1 = (kb + 4 < KD) ? *(const float4*)(agp + k0 + 4)
                            : make_float4(0.f, 0.f, 0.f, 0.f);

        cp_async16(bdst0 + stg_off,      bgp + k0);
        cp_async16(bdst0 + stg_off + 16, bgp + k0 + 8);
        cp_commit();

        if (c > 0) compute_stage<2>(sb + (uint32_t)((c - 1) & 1) * STAGE_BYTES,
                                    wm, wn, lrow, lk, acc);

        {
            const uint32_t off = stg_off + AHI_OFF
                               + ((uint32_t)arow * RS + aq * 8) * 2;
            __half2 h01 = __floats2half2_rn(ap0.x, ap0.y);
            __half2 h23 = __floats2half2_rn(ap0.z, ap0.w);
            __half2 h45 = __floats2half2_rn(ap1.x, ap1.y);
            __half2 h67 = __floats2half2_rn(ap1.z, ap1.w);
            __half2 l01 = __floats2half2_rn(ap0.x - __low2float(h01),
                                            ap0.y - __high2float(h01));
            __half2 l23 = __floats2half2_rn(ap0.z - __low2float(h23),
                                            ap0.w - __high2float(h23));
            __half2 l45 = __floats2half2_rn(ap1.x - __low2float(h45),
                                            ap1.y - __high2float(h45));
            __half2 l67 = __floats2half2_rn(ap1.z - __low2float(h67),
                                            ap1.w - __high2float(h67));
            *(uint4*)(smem + off) = make_uint4(
                *(uint32_t*)&h01, *(uint32_t*)&h23,
                *(uint32_t*)&h45, *(uint32_t*)&h67);
            *(uint4*)(smem + off + (ALO_OFF - AHI_OFF)) = make_uint4(
                *(uint32_t*)&l01, *(uint32_t*)&l23,
                *(uint32_t*)&l45, *(uint32_t*)&l67);
        }
        cp_wait0();
        __syncthreads();
    }
    // last chunk (k0=288): only k-step 0 is real (k 288..304 covers KD=300)
    compute_stage<1>(sb + (uint32_t)((NCHUNK - 1) & 1) * STAGE_BYTES,
                     wm, wn, lrow, lk, acc);

    // Epilogue: bias + ReLU -> global; column sums -> g_mean (fused mean)
    const int trow = lid >> 2, tcol = (lid & 3) * 2;
    float bcol[4][2];
    #pragma unroll
    for (int nf = 0; nf < 4; ++nf) {
        bcol[nf][0] = __ldg(bias + wn * 32 + nf * 8 + tcol);
        bcol[nf][1] = __ldg(bias + wn * 32 + nf * 8 + tcol + 1);
    }
    float cs[4][2];
    #pragma unroll
    for (int nf = 0; nf < 4; ++nf) { cs[nf][0] = 0.f; cs[nf][1] = 0.f; }

    float* Cb = g_t[side];
    #pragma unroll
    for (int mf = 0; mf < 2; ++mf) {
        const int r0 = rowBase + wm * 32 + mf * 16 + trow;
        #pragma unroll
        for (int nf = 0; nf < 4; ++nf) {
            const int c0 = wn * 32 + nf * 8 + tcol;
            float2 v0, v1;
            v0.x = fmaxf(acc[mf][nf][0] + bcol[nf][0], 0.f);
            v0.y = fmaxf(acc[mf][nf][1] + bcol[nf][1], 0.f);
            v1.x = fmaxf(acc[mf][nf][2] + bcol[nf][0], 0.f);
            v1.y = fmaxf(acc[mf][nf][3] + bcol[nf][1], 0.f);
            *(float2*)(Cb + (size_t)r0 * ND + c0)       = v0;
            *(float2*)(Cb + (size_t)(r0 + 8) * ND + c0) = v1;
            cs[nf][0] += v0.x + v1.x;
            cs[nf][1] += v0.y + v1.y;
        }
    }
    #pragma unroll
    for (int o = 4; o <= 16; o <<= 1)
        #pragma unroll
        for (int nf = 0; nf < 4; ++nf) {
            cs[nf][0] += __shfl_xor_sync(0xffffffffu, cs[nf][0], o);
            cs[nf][1] += __shfl_xor_sync(0xffffffffu, cs[nf][1], o);
        }
    if (lid < 4) {
        const int b = blockIdx.x / (MTOK / BM);   // 20 M-tiles per sample
        float* mptr = g_mean[side] + b * ND + wn * 32;
        #pragma unroll
        for (int nf = 0; nf < 4; ++nf) {
            atomicAdd(mptr + nf * 8 + tcol,     cs[nf][0]);
            atomicAdd(mptr + nf * 8 + tcol + 1, cs[nf][1]);
        }
    }
}

// ---------------------------------------------------------------------------
// Kernel 2: attention per review — two coalesced float4 passes over g_t,
// skipping masked tokens (weight exactly 0) in both passes.
// Grid (320, 2), 128 threads.
// ---------------------------------------------------------------------------
__global__ __launch_bounds__(128) void attn_kernel(
    const int* __restrict__ mask_a, const int* __restrict__ mask_b,
    float* __restrict__ out)
{
    __shared__ __align__(16) float meanv[128];
    __shared__ __align__(16) float part[4][128];
    __shared__ float sc[128], wv[128], red[8];
    __shared__ int msk[128];

    const int side = blockIdx.y;
    const int n    = blockIdx.x;
    const int b    = n / RV_NUM;
    const int tid  = threadIdx.x;
    const int lane = tid & 31, w = tid >> 5;

    const float* __restrict__ T = g_t[side] + (size_t)n * RV_LEN * ND;
    const int*   __restrict__ mask = side ? mask_b : mask_a;

    meanv[tid] = g_mean[side ^ 1][b * ND + tid] * (1.0f / (float)MTOK);
    msk[tid]   = mask[n * RV_LEN + tid];
    __syncthreads();

    const float4 mv = *(const float4*)&meanv[lane * 4];

    // Pass 1: scores (skip masked tokens — their score is replaced by -1e9).
    #pragma unroll 4
    for (int t = 0; t < 32; ++t) {
        const int l = w * 32 + t;
        if (msk[l]) {
            float4 x = *(const float4*)(T + (size_t)l * ND + lane * 4);
            float p = x.x * mv.x + x.y * mv.y + x.z * mv.z + x.w * mv.w;
            #pragma unroll
            for (int o = 16; o; o >>= 1) p += __shfl_xor_sync(0xffffffffu, p, o);
            if (lane == 0) sc[l] = p;
        }
    }
    __syncthreads();

    // Masked softmax over this review's 128 tokens (thread = token).
    float logit = (msk[tid] > 0) ? sc[tid] : -1e9f;
    float v = logit;
    #pragma unroll
    for (int o = 16; o; o >>= 1) v = fmaxf(v, __shfl_xor_sync(0xffffffffu, v, o));
    if (lane == 0) red[w] = v;
    __syncthreads();
    const float gmax = fmaxf(fmaxf(red[0], red[1]), fmaxf(red[2], red[3]));

    const float e = __expf(logit - gmax);   // exactly 0 for masked tokens
    v = e;
    #pragma unroll
    for (int o = 16; o; o >>= 1) v += __shfl_xor_sync(0xffffffffu, v, o);
    if (lane == 0) red[4 + w] = v;
    __syncthreads();
    const float gsum = red[4] + red[5] + red[6] + red[7];

    const float wgt = e / gsum;
    wv[tid] = wgt;
    out[(size_t)(2 + side) * ROWS + (size_t)n * RV_LEN + tid] = wgt;
    __syncthreads();

    // Pass 2: weighted sum, skipping zero-weight rows (exact-0 contributions).
    float4 acc = make_float4(0.f, 0.f, 0.f, 0.f);
    #pragma unroll 4
    for (int l = w; l < RV_LEN; l += 4) {
        const float wl = wv[l];
        if (wl != 0.f) {
            float4 x = *(const float4*)(T + (size_t)l * ND + lane * 4);
            acc.x += wl * x.x; acc.y += wl * x.y;
            acc.z += wl * x.z; acc.w += wl * x.w;
        }
    }
    *(float4*)&part[w][lane * 4] = acc;
    __syncthreads();
    float s = part[0][tid] + part[1][tid] + part[2][tid] + part[3][tid];
    out[(size_t)side * ROWS + (size_t)n * ND + tid] = s;
}

// ---------------------------------------------------------------------------
extern "C" void kernel_launch(void* const* d_in, const int* in_sizes, int n_in,
                              void* d_out, int out_size)
{
    const float* seq_a  = (const float*)d_in[0];
    const float* seq_b  = (const float*)d_in[1];
    const int*   mask_a = (const int*)d_in[2];
    const int*   mask_b = (const int*)d_in[3];
    const float* W      = (const float*)d_in[4];
    const float* bias   = (const float*)d_in[5];
    float* out = (float*)d_out;

    cudaFuncSetAttribute(gemm_mma_kernel, cudaFuncAttributeMaxDynamicSharedMemorySize, GEMM_SMEM);

    prep_w_kernel<<<160, 256>>>(W);

    dim3 g1(ROWS / BM, 2);
    gemm_mma_kernel<<<g1, 256, GEMM_SMEM>>>(seq_a, seq_b, bias);

    dim3 g3(NREV, 2);
    attn_kernel<<<g3, 128>>>(mask_a, mask_b, out);
}

// round 16
// speedup vs baseline: 1.1378x; 1.0476x over previous
#include <cuda_runtime.h>
#include <cuda_fp16.h>
#include <cstdint>

#define RV_NUM 10
#define RV_LEN 128
#define BZ     32
#define NREV   (BZ * RV_NUM)      // 320 reviews
#define ROWS   (NREV * RV_LEN)    // 40960 tokens per tensor
#define KD     300                // in_feat
#define KPAD   320                // padded K (multiple of 32)
#define ND     128                // out_feat / hdim
#define MTOK   (RV_NUM * RV_LEN)  // 1280 tokens per sample

// Scratch (no runtime allocs): transformed features, mean accumulators, W fp16.
__device__ float g_t[2][ROWS * ND];       // ta / tb (~42 MB, L2-resident)
__device__ float g_mean[2][BZ * ND];      // SUM of transformed feats (atomics)
__device__ __half g_wt_hi[ND * KPAD];     // W^T rounded to fp16  [n][k]

// ---------------------------------------------------------------------------
// PTX helpers (sm_103 base target: NO tcgen05; mma.sync / ldmatrix / cp.async)
// ---------------------------------------------------------------------------
__device__ __forceinline__ uint32_t smem_u32(const void* p) {
    uint32_t a;
    asm("{ .reg .u64 t; cvta.to.shared.u64 t, %1; cvt.u32.u64 %0, t; }"
        : "=r"(a) : "l"(p));
    return a;
}
__device__ __forceinline__ void cp_async16(uint32_t dst, const void* src) {
    asm volatile("cp.async.cg.shared.global [%0], [%1], 16;"
                 :: "r"(dst), "l"(src) : "memory");
}
__device__ __forceinline__ void cp_commit() {
    asm volatile("cp.async.commit_group;" ::: "memory");
}
__device__ __forceinline__ void cp_wait0() {
    asm volatile("cp.async.wait_group 0;" ::: "memory");
}
__device__ __forceinline__ void ldmx4(uint32_t addr, uint32_t r[4]) {
    asm volatile("ldmatrix.sync.aligned.m8n8.x4.shared.b16 {%0,%1,%2,%3}, [%4];"
                 : "=r"(r[0]), "=r"(r[1]), "=r"(r[2]), "=r"(r[3]) : "r"(addr));
}
__device__ __forceinline__ void mma16816(float d[4], const uint32_t a[4],
                                         uint32_t b0, uint32_t b1) {
    asm volatile(
        "mma.sync.aligned.m16n8k16.row.col.f32.f16.f16.f32 "
        "{%0,%1,%2,%3}, {%4,%5,%6,%7}, {%8,%9}, {%0,%1,%2,%3};"
        : "+f"(d[0]), "+f"(d[1]), "+f"(d[2]), "+f"(d[3])
        : "r"(a[0]), "r"(a[1]), "r"(a[2]), "r"(a[3]), "r"(b0), "r"(b1));
}

// ---------------------------------------------------------------------------
// Kernel 0: transpose W [300,128] f32 -> fp16 [128,320]; zero g_mean.
// Read side fully coalesced (W[gid]); strided 2B stores are fire-and-forget.
// ---------------------------------------------------------------------------
__global__ __launch_bounds__(256) void prep_w_kernel(const float* __restrict__ W)
{
    int gid = blockIdx.x * 256 + threadIdx.x;   // 160 * 256 = 40960
    if (gid < 2 * BZ * ND) ((float*)g_mean)[gid] = 0.f;
    int k = gid >> 7;          // 0..319
    int n = gid & 127;
    float v = (k < KD) ? W[k * ND + n] : 0.f;   // == W[gid] when k < KD
    g_wt_hi[(size_t)n * KPAD + k] = __float2half_rn(v);
}

// ---------------------------------------------------------------------------
// Kernel 1: HMMA GEMM  T = relu(X @ W + b), fp16 2-pass (A split hi/lo), fp32
// accum. M-tile 64: grid (640, 2), 256 threads, 8 warps as 2(m) x 4(n),
// warp tile 32x32, __launch_bounds__(256,3): 3 CTAs/SM (proven optimum).
// K trimmed: chunks 0..8 full (k<288), chunk 9 runs 1 k-step (k 288..304;
// real data ends at 300, rest exact zeros). Epilogue: bias+ReLU + fused mean.
// ---------------------------------------------------------------------------
#define BM 64
#define BK 32
#define NCHUNK (KPAD / BK)            // 10
#define RS 40                         // fp16/row (80B rows: LDSM conflict-free)
#define AHI_OFF 0
#define ALO_OFF (BM * RS * 2)         // 5120
#define BHI_OFF (2 * BM * RS * 2)     // 10240
#define STAGE_BYTES (BHI_OFF + 128 * RS * 2)  // 20480
#define GEMM_SMEM (2 * STAGE_BYTES)   // 40960

// Per (p): 4 hi-MMAs then 4 lo-MMAs -> same-accumulator reuse distance 4.
template <int NKS>
__device__ __forceinline__ void compute_stage(
    uint32_t stgc, int wm, int wn, int lrow, int lk, float acc[2][4][4])
{
    #pragma unroll
    for (int ks = 0; ks < NKS; ++ks) {
        uint32_t ah[2][4], al[2][4];
        #pragma unroll
        for (int mf = 0; mf < 2; ++mf) {
            uint32_t ad = stgc + AHI_OFF
                        + ((uint32_t)(wm * 32 + mf * 16 + lrow) * RS + ks * 16 + lk) * 2;
            ldmx4(ad, ah[mf]);
            ldmx4(ad + (ALO_OFF - AHI_OFF), al[mf]);
        }
        #pragma unroll
        for (int p = 0; p < 2; ++p) {
            uint32_t bd = stgc + BHI_OFF
                        + ((uint32_t)(wn * 32 + p * 16 + lrow) * RS + ks * 16 + lk) * 2;
            uint32_t rh[4];
            ldmx4(bd, rh);
            #pragma unroll
            for (int j = 0; j < 2; ++j)
                #pragma unroll
                for (int mf = 0; mf < 2; ++mf)
                    mma16816(acc[mf][2 * p + j], ah[mf], rh[j], rh[j + 2]);
            #pragma unroll
            for (int j = 0; j < 2; ++j)
                #pragma unroll
                for (int mf = 0; mf < 2; ++mf)
                    mma16816(acc[mf][2 * p + j], al[mf], rh[j], rh[j + 2]);
        }
    }
}

__global__ __launch_bounds__(256, 3) void gemm_mma_kernel(
    const float* __restrict__ A0, const float* __restrict__ A1,
    const float* __restrict__ bias)
{
    extern __shared__ char smem[];
    const uint32_t sb = smem_u32(smem);
    const int tid = threadIdx.x, wid = tid >> 5, lid = tid & 31;
    const int side = blockIdx.y;
    const int rowBase = blockIdx.x * BM;
    const float* __restrict__ A = side ? A1 : A0;

    const int wm = wid >> 2, wn = wid & 3;       // warp grid 2 x 4
    const int g = lid >> 3, lr = lid & 7;
    const int lrow = (g & 1) * 8 + lr;           // ldmatrix row within 16-frag
    const int lk   = (g >> 1) * 8;               // ldmatrix k offset within 16

    float acc[2][4][4];
    #pragma unroll
    for (int i = 0; i < 2; ++i)
        #pragma unroll
        for (int j = 0; j < 4; ++j)
            #pragma unroll
            for (int q = 0; q < 4; ++q) acc[i][j][q] = 0.f;

    // A loader: thread covers row=tid/4 (0..63), k-quarter=tid%4 (8 floats)
    const int arow = tid >> 2, aq = tid & 3;
    const float* agp = A + (size_t)(rowBase + arow) * KD + aq * 8;
    // B loader: thread covers row=tid/2 (0..127), k-half=tid%2 (16 halfs)
    const int bn = tid >> 1, bq = tid & 1;
    const __half* bgp = g_wt_hi + (size_t)bn * KPAD + bq * 16;
    const uint32_t bdst0 = sb + BHI_OFF + (uint32_t)bn * RS * 2 + bq * 32;

    float4 ap0, ap1;

    for (int c = 0; c < NCHUNK; ++c) {
        const int k0 = c * BK;
        const uint32_t stg_off = (uint32_t)(c & 1) * STAGE_BYTES;

        const int kb = k0 + aq * 8;
        ap0 = (kb < KD)     ? *(const float4*)(agp + k0)
                            : make_float4(0.f, 0.f, 0.f, 0.f);
        ap1 = (kb + 4 < KD) ? *(const float4*)(agp + k0 + 4)
                            : make_float4(0.f, 0.f, 0.f, 0.f);

        cp_async16(bdst0 + stg_off,      bgp + k0);
        cp_async16(bdst0 + stg_off + 16, bgp + k0 + 8);
        cp_commit();

        if (c > 0) compute_stage<2>(sb + (uint32_t)((c - 1) & 1) * STAGE_BYTES,
                                    wm, wn, lrow, lk, acc);

        {
            const uint32_t off = stg_off + AHI_OFF
                               + ((uint32_t)arow * RS + aq * 8) * 2;
            __half2 h01 = __floats2half2_rn(ap0.x, ap0.y);
            __half2 h23 = __floats2half2_rn(ap0.z, ap0.w);
            __half2 h45 = __floats2half2_rn(ap1.x, ap1.y);
            __half2 h67 = __floats2half2_rn(ap1.z, ap1.w);
            __half2 l01 = __floats2half2_rn(ap0.x - __low2float(h01),
                                            ap0.y - __high2float(h01));
            __half2 l23 = __floats2half2_rn(ap0.z - __low2float(h23),
                                            ap0.w - __high2float(h23));
            __half2 l45 = __floats2half2_rn(ap1.x - __low2float(h45),
                                            ap1.y - __high2float(h45));
            __half2 l67 = __floats2half2_rn(ap1.z - __low2float(h67),
                                            ap1.w - __high2float(h67));
            *(uint4*)(smem + off) = make_uint4(
                *(uint32_t*)&h01, *(uint32_t*)&h23,
                *(uint32_t*)&h45, *(uint32_t*)&h67);
            *(uint4*)(smem + off + (ALO_OFF - AHI_OFF)) = make_uint4(
                *(uint32_t*)&l01, *(uint32_t*)&l23,
                *(uint32_t*)&l45, *(uint32_t*)&l67);
        }
        cp_wait0();
        __syncthreads();
    }
    // last chunk (k0=288): only k-step 0 is real (k 288..304 covers KD=300)
    compute_stage<1>(sb + (uint32_t)((NCHUNK - 1) & 1) * STAGE_BYTES,
                     wm, wn, lrow, lk, acc);

    // Epilogue: bias + ReLU -> global; column sums -> g_mean (fused mean)
    const int trow = lid >> 2, tcol = (lid & 3) * 2;
    float bcol[4][2];
    #pragma unroll
    for (int nf = 0; nf < 4; ++nf) {
        bcol[nf][0] = __ldg(bias + wn * 32 + nf * 8 + tcol);
        bcol[nf][1] = __ldg(bias + wn * 32 + nf * 8 + tcol + 1);
    }
    float cs[4][2];
    #pragma unroll
    for (int nf = 0; nf < 4; ++nf) { cs[nf][0] = 0.f; cs[nf][1] = 0.f; }

    float* Cb = g_t[side];
    #pragma unroll
    for (int mf = 0; mf < 2; ++mf) {
        const int r0 = rowBase + wm * 32 + mf * 16 + trow;
        #pragma unroll
        for (int nf = 0; nf < 4; ++nf) {
            const int c0 = wn * 32 + nf * 8 + tcol;
            float2 v0, v1;
            v0.x = fmaxf(acc[mf][nf][0] + bcol[nf][0], 0.f);
            v0.y = fmaxf(acc[mf][nf][1] + bcol[nf][1], 0.f);
            v1.x = fmaxf(acc[mf][nf][2] + bcol[nf][0], 0.f);
            v1.y = fmaxf(acc[mf][nf][3] + bcol[nf][1], 0.f);
            *(float2*)(Cb + (size_t)r0 * ND + c0)       = v0;
            *(float2*)(Cb + (size_t)(r0 + 8) * ND + c0) = v1;
            cs[nf][0] += v0.x + v1.x;
            cs[nf][1] += v0.y + v1.y;
        }
    }
    #pragma unroll
    for (int o = 4; o <= 16; o <<= 1)
        #pragma unroll
        for (int nf = 0; nf < 4; ++nf) {
            cs[nf][0] += __shfl_xor_sync(0xffffffffu, cs[nf][0], o);
            cs[nf][1] += __shfl_xor_sync(0xffffffffu, cs[nf][1], o);
        }
    if (lid < 4) {
        const int b = blockIdx.x / (MTOK / BM);   // 20 M-tiles per sample
        float* mptr = g_mean[side] + b * ND + wn * 32;
        #pragma unroll
        for (int nf = 0; nf < 4; ++nf) {
            atomicAdd(mptr + nf * 8 + tcol,     cs[nf][0]);
            atomicAdd(mptr + nf * 8 + tcol + 1, cs[nf][1]);
        }
    }
}

// ---------------------------------------------------------------------------
// Kernel 2: attention per review — two coalesced float4 passes over g_t.
// Branch-free (R11 version: full MLP, no mask-dependent load skipping).
// Grid (320, 2), 128 threads.
// ---------------------------------------------------------------------------
__global__ __launch_bounds__(128) void attn_kernel(
    const int* __restrict__ mask_a, const int* __restrict__ mask_b,
    float* __restrict__ out)
{
    __shared__ __align__(16) float meanv[128];
    __shared__ __align__(16) float part[4][128];
    __shared__ float sc[128], wv[128], red[8];

    const int side = blockIdx.y;
    const int n    = blockIdx.x;
    const int b    = n / RV_NUM;
    const int tid  = threadIdx.x;
    const int lane = tid & 31, w = tid >> 5;

    const float* __restrict__ T = g_t[side] + (size_t)n * RV_LEN * ND;
    const int*   __restrict__ mask = side ? mask_b : mask_a;

    meanv[tid] = g_mean[side ^ 1][b * ND + tid] * (1.0f / (float)MTOK);
    __syncthreads();

    const float4 mv = *(const float4*)&meanv[lane * 4];

    // Pass 1: scores. Warp w covers tokens [w*32, w*32+32); lanes split the row.
    #pragma unroll 8
    for (int t = 0; t < 32; ++t) {
        const int l = w * 32 + t;
        float4 x = *(const float4*)(T + (size_t)l * ND + lane * 4);
        float p = x.x * mv.x + x.y * mv.y + x.z * mv.z + x.w * mv.w;
        #pragma unroll
        for (int o = 16; o; o >>= 1) p += __shfl_xor_sync(0xffffffffu, p, o);
        if (lane == 0) sc[l] = p;
    }
    __syncthreads();

    // Masked softmax over this review's 128 tokens (thread = token).
    float logit = (mask[n * RV_LEN + tid] > 0) ? sc[tid] : -1e9f;
    float v = logit;
    #pragma unroll
    for (int o = 16; o; o >>= 1) v = fmaxf(v, __shfl_xor_sync(0xffffffffu, v, o));
    if (lane == 0) red[w] = v;
    __syncthreads();
    const float gmax = fmaxf(fmaxf(red[0], red[1]), fmaxf(red[2], red[3]));

    const float e = __expf(logit - gmax);
    v = e;
    #pragma unroll
    for (int o = 16; o; o >>= 1) v += __shfl_xor_sync(0xffffffffu, v, o);
    if (lane == 0) red[4 + w] = v;
    __syncthreads();
    const float gsum = red[4] + red[5] + red[6] + red[7];

    const float wgt = e / gsum;
    wv[tid] = wgt;
    out[(size_t)(2 + side) * ROWS + (size_t)n * RV_LEN + tid] = wgt;
    __syncthreads();

    // Pass 2: weighted sum. Row-group w handles rows l ≡ w (mod 4), lanes split d.
    float4 acc = make_float4(0.f, 0.f, 0.f, 0.f);
    #pragma unroll 8
    for (int l = w; l < RV_LEN; l += 4) {
        float4 x = *(const float4*)(T + (size_t)l * ND + lane * 4);
        const float wl = wv[l];
        acc.x += wl * x.x; acc.y += wl * x.y;
        acc.z += wl * x.z; acc.w += wl * x.w;
    }
    *(float4*)&part[w][lane * 4] = acc;
    __syncthreads();
    float s = part[0][tid] + part[1][tid] + part[2][tid] + part[3][tid];
    out[(size_t)side * ROWS + (size_t)n * ND + tid] = s;
}

// ---------------------------------------------------------------------------
extern "C" void kernel_launch(void* const* d_in, const int* in_sizes, int n_in,
                              void* d_out, int out_size)
{
    const float* seq_a  = (const float*)d_in[0];
    const float* seq_b  = (const float*)d_in[1];
    const int*   mask_a = (const int*)d_in[2];
    const int*   mask_b = (const int*)d_in[3];
    const float* W      = (const float*)d_in[4];
    const float* bias   = (const float*)d_in[5];
    float* out = (float*)d_out;

    cudaFuncSetAttribute(gemm_mma_kernel, cudaFuncAttributeMaxDynamicSharedMemorySize, GEMM_SMEM);

    prep_w_kernel<<<160, 256>>>(W);

    dim3 g1(ROWS / BM, 2);
    gemm_mma_kernel<<<g1, 256, GEMM_SMEM>>>(seq_a, seq_b, bias);

    dim3 g3(NREV, 2);
    attn_kernel<<<g3, 128>>>(mask_a, mask_b, out);
}

// round 17
// speedup vs baseline: 1.2316x; 1.0825x over previous
#include <cuda_runtime.h>
#include <cuda_fp16.h>
#include <cstdint>

#define RV_NUM 10
#define RV_LEN 128
#define BZ     32
#define NREV   (BZ * RV_NUM)      // 320 reviews
#define ROWS   (NREV * RV_LEN)    // 40960 tokens per tensor
#define KD     300                // in_feat
#define KPAD   320                // padded K (multiple of 32)
#define ND     128                // out_feat / hdim
#define MTOK   (RV_NUM * RV_LEN)  // 1280 tokens per sample

// Scratch (no runtime allocs): transformed features, mean accumulators, W fp16.
__device__ float g_t[2][ROWS * ND];       // ta / tb (~42 MB, L2-resident)
__device__ float g_mean[2][BZ * ND];      // SUM of transformed feats (atomics)
__device__ __half g_wt_hi[ND * KPAD];     // W^T rounded to fp16  [n][k]

// ---------------------------------------------------------------------------
// PTX helpers (sm_103 base target: NO tcgen05; mma.sync / ldmatrix / cp.async)
// ---------------------------------------------------------------------------
__device__ __forceinline__ uint32_t smem_u32(const void* p) {
    uint32_t a;
    asm("{ .reg .u64 t; cvta.to.shared.u64 t, %1; cvt.u32.u64 %0, t; }"
        : "=r"(a) : "l"(p));
    return a;
}
__device__ __forceinline__ void cp_async16(uint32_t dst, const void* src) {
    asm volatile("cp.async.cg.shared.global [%0], [%1], 16;"
                 :: "r"(dst), "l"(src) : "memory");
}
__device__ __forceinline__ void cp_commit() {
    asm volatile("cp.async.commit_group;" ::: "memory");
}
__device__ __forceinline__ void cp_wait0() {
    asm volatile("cp.async.wait_group 0;" ::: "memory");
}
__device__ __forceinline__ void ldmx4(uint32_t addr, uint32_t r[4]) {
    asm volatile("ldmatrix.sync.aligned.m8n8.x4.shared.b16 {%0,%1,%2,%3}, [%4];"
                 : "=r"(r[0]), "=r"(r[1]), "=r"(r[2]), "=r"(r[3]) : "r"(addr));
}
__device__ __forceinline__ void mma16816(float d[4], const uint32_t a[4],
                                         uint32_t b0, uint32_t b1) {
    asm volatile(
        "mma.sync.aligned.m16n8k16.row.col.f32.f16.f16.f32 "
        "{%0,%1,%2,%3}, {%4,%5,%6,%7}, {%8,%9}, {%0,%1,%2,%3};"
        : "+f"(d[0]), "+f"(d[1]), "+f"(d[2]), "+f"(d[3])
        : "r"(a[0]), "r"(a[1]), "r"(a[2]), "r"(a[3]), "r"(b0), "r"(b1));
}

// ---------------------------------------------------------------------------
// Kernel 0: transpose W [300,128] f32 -> fp16 [128,320]; zero g_mean.
// Read side fully coalesced (W[gid]); strided 2B stores are fire-and-forget.
// ---------------------------------------------------------------------------
__global__ __launch_bounds__(256) void prep_w_kernel(const float* __restrict__ W)
{
    int gid = blockIdx.x * 256 + threadIdx.x;   // 160 * 256 = 40960
    if (gid < 2 * BZ * ND) ((float*)g_mean)[gid] = 0.f;
    int k = gid >> 7;          // 0..319
    int n = gid & 127;
    float v = (k < KD) ? W[k * ND + n] : 0.f;   // == W[gid] when k < KD
    g_wt_hi[(size_t)n * KPAD + k] = __float2half_rn(v);
}

// ---------------------------------------------------------------------------
// Kernel 1: HMMA GEMM  T = relu(X @ W + b), fp16 2-pass (A split hi/lo), fp32
// accum. M-tile 64: grid (640, 2), 256 threads, 8 warps as 2(m) x 4(n),
// warp tile 32x32, __launch_bounds__(256,3): 3 CTAs/SM (proven optimum).
// K trimmed: chunks 0..8 full, chunk 9 runs 1 k-step (k 288..304 covers 300).
// Epilogue: bias+ReLU + fused mean atomics.
// ---------------------------------------------------------------------------
#define BM 64
#define BK 32
#define NCHUNK (KPAD / BK)            // 10
#define RS 40                         // fp16/row (80B rows: LDSM conflict-free)
#define AHI_OFF 0
#define ALO_OFF (BM * RS * 2)         // 5120
#define BHI_OFF (2 * BM * RS * 2)     // 10240
#define STAGE_BYTES (BHI_OFF + 128 * RS * 2)  // 20480
#define GEMM_SMEM (2 * STAGE_BYTES)   // 40960

// Per (p): 4 hi-MMAs then 4 lo-MMAs -> same-accumulator reuse distance 4.
template <int NKS>
__device__ __forceinline__ void compute_stage(
    uint32_t stgc, int wm, int wn, int lrow, int lk, float acc[2][4][4])
{
    #pragma unroll
    for (int ks = 0; ks < NKS; ++ks) {
        uint32_t ah[2][4], al[2][4];
        #pragma unroll
        for (int mf = 0; mf < 2; ++mf) {
            uint32_t ad = stgc + AHI_OFF
                        + ((uint32_t)(wm * 32 + mf * 16 + lrow) * RS + ks * 16 + lk) * 2;
            ldmx4(ad, ah[mf]);
            ldmx4(ad + (ALO_OFF - AHI_OFF), al[mf]);
        }
        #pragma unroll
        for (int p = 0; p < 2; ++p) {
            uint32_t bd = stgc + BHI_OFF
                        + ((uint32_t)(wn * 32 + p * 16 + lrow) * RS + ks * 16 + lk) * 2;
            uint32_t rh[4];
            ldmx4(bd, rh);
            #pragma unroll
            for (int j = 0; j < 2; ++j)
                #pragma unroll
                for (int mf = 0; mf < 2; ++mf)
                    mma16816(acc[mf][2 * p + j], ah[mf], rh[j], rh[j + 2]);
            #pragma unroll
            for (int j = 0; j < 2; ++j)
                #pragma unroll
                for (int mf = 0; mf < 2; ++mf)
                    mma16816(acc[mf][2 * p + j], al[mf], rh[j], rh[j + 2]);
        }
    }
}

__global__ __launch_bounds__(256, 3) void gemm_mma_kernel(
    const float* __restrict__ A0, const float* __restrict__ A1,
    const float* __restrict__ bias)
{
    extern __shared__ char smem[];
    const uint32_t sb = smem_u32(smem);
    const int tid = threadIdx.x, wid = tid >> 5, lid = tid & 31;
    const int side = blockIdx.y;
    const int rowBase = blockIdx.x * BM;
    const float* __restrict__ A = side ? A1 : A0;

    const int wm = wid >> 2, wn = wid & 3;       // warp grid 2 x 4
    const int g = lid >> 3, lr = lid & 7;
    const int lrow = (g & 1) * 8 + lr;           // ldmatrix row within 16-frag
    const int lk   = (g >> 1) * 8;               // ldmatrix k offset within 16

    float acc[2][4][4];
    #pragma unroll
    for (int i = 0; i < 2; ++i)
        #pragma unroll
        for (int j = 0; j < 4; ++j)
            #pragma unroll
            for (int q = 0; q < 4; ++q) acc[i][j][q] = 0.f;

    // A loader: thread covers row=tid/4 (0..63), k-quarter=tid%4 (8 floats)
    const int arow = tid >> 2, aq = tid & 3;
    const float* agp = A + (size_t)(rowBase + arow) * KD + aq * 8;
    // B loader: thread covers row=tid/2 (0..127), k-half=tid%2 (16 halfs)
    const int bn = tid >> 1, bq = tid & 1;
    const __half* bgp = g_wt_hi + (size_t)bn * KPAD + bq * 16;
    const uint32_t bdst0 = sb + BHI_OFF + (uint32_t)bn * RS * 2 + bq * 32;

    float4 ap0, ap1;

    for (int c = 0; c < NCHUNK; ++c) {
        const int k0 = c * BK;
        const uint32_t stg_off = (uint32_t)(c & 1) * STAGE_BYTES;

        const int kb = k0 + aq * 8;
        ap0 = (kb < KD)     ? *(const float4*)(agp + k0)
                            : make_float4(0.f, 0.f, 0.f, 0.f);
        ap1 = (kb + 4 < KD) ? *(const float4*)(agp + k0 + 4)
                            : make_float4(0.f, 0.f, 0.f, 0.f);

        cp_async16(bdst0 + stg_off,      bgp + k0);
        cp_async16(bdst0 + stg_off + 16, bgp + k0 + 8);
        cp_commit();

        if (c > 0) compute_stage<2>(sb + (uint32_t)((c - 1) & 1) * STAGE_BYTES,
                                    wm, wn, lrow, lk, acc);

        {
            const uint32_t off = stg_off + AHI_OFF
                               + ((uint32_t)arow * RS + aq * 8) * 2;
            __half2 h01 = __floats2half2_rn(ap0.x, ap0.y);
            __half2 h23 = __floats2half2_rn(ap0.z, ap0.w);
            __half2 h45 = __floats2half2_rn(ap1.x, ap1.y);
            __half2 h67 = __floats2half2_rn(ap1.z, ap1.w);
            __half2 l01 = __floats2half2_rn(ap0.x - __low2float(h01),
                                            ap0.y - __high2float(h01));
            __half2 l23 = __floats2half2_rn(ap0.z - __low2float(h23),
                                            ap0.w - __high2float(h23));
            __half2 l45 = __floats2half2_rn(ap1.x - __low2float(h45),
                                            ap1.y - __high2float(h45));
            __half2 l67 = __floats2half2_rn(ap1.z - __low2float(h67),
                                            ap1.w - __high2float(h67));
            *(uint4*)(smem + off) = make_uint4(
                *(uint32_t*)&h01, *(uint32_t*)&h23,
                *(uint32_t*)&h45, *(uint32_t*)&h67);
            *(uint4*)(smem + off + (ALO_OFF - AHI_OFF)) = make_uint4(
                *(uint32_t*)&l01, *(uint32_t*)&l23,
                *(uint32_t*)&l45, *(uint32_t*)&l67);
        }
        cp_wait0();
        __syncthreads();
    }
    // last chunk (k0=288): only k-step 0 is real (k 288..304 covers KD=300)
    compute_stage<1>(sb + (uint32_t)((NCHUNK - 1) & 1) * STAGE_BYTES,
                     wm, wn, lrow, lk, acc);

    // Epilogue: bias + ReLU -> global; column sums -> g_mean (fused mean)
    const int trow = lid >> 2, tcol = (lid & 3) * 2;
    float bcol[4][2];
    #pragma unroll
    for (int nf = 0; nf < 4; ++nf) {
        bcol[nf][0] = __ldg(bias + wn * 32 + nf * 8 + tcol);
        bcol[nf][1] = __ldg(bias + wn * 32 + nf * 8 + tcol + 1);
    }
    float cs[4][2];
    #pragma unroll
    for (int nf = 0; nf < 4; ++nf) { cs[nf][0] = 0.f; cs[nf][1] = 0.f; }

    float* Cb = g_t[side];
    #pragma unroll
    for (int mf = 0; mf < 2; ++mf) {
        const int r0 = rowBase + wm * 32 + mf * 16 + trow;
        #pragma unroll
        for (int nf = 0; nf < 4; ++nf) {
            const int c0 = wn * 32 + nf * 8 + tcol;
            float2 v0, v1;
            v0.x = fmaxf(acc[mf][nf][0] + bcol[nf][0], 0.f);
            v0.y = fmaxf(acc[mf][nf][1] + bcol[nf][1], 0.f);
            v1.x = fmaxf(acc[mf][nf][2] + bcol[nf][0], 0.f);
            v1.y = fmaxf(acc[mf][nf][3] + bcol[nf][1], 0.f);
            *(float2*)(Cb + (size_t)r0 * ND + c0)       = v0;
            *(float2*)(Cb + (size_t)(r0 + 8) * ND + c0) = v1;
            cs[nf][0] += v0.x + v1.x;
            cs[nf][1] += v0.y + v1.y;
        }
    }
    #pragma unroll
    for (int o = 4; o <= 16; o <<= 1)
        #pragma unroll
        for (int nf = 0; nf < 4; ++nf) {
            cs[nf][0] += __shfl_xor_sync(0xffffffffu, cs[nf][0], o);
            cs[nf][1] += __shfl_xor_sync(0xffffffffu, cs[nf][1], o);
        }
    if (lid < 4) {
        const int b = blockIdx.x / (MTOK / BM);   // 20 M-tiles per sample
        float* mptr = g_mean[side] + b * ND + wn * 32;
        #pragma unroll
        for (int nf = 0; nf < 4; ++nf) {
            atomicAdd(mptr + nf * 8 + tcol,     cs[nf][0]);
            atomicAdd(mptr + nf * 8 + tcol + 1, cs[nf][1]);
        }
    }
}

// ---------------------------------------------------------------------------
// Kernel 2: attention per review — register-resident tile: g_t read ONCE.
// 256 threads: warp w owns tokens [w*16, w*16+16); lane owns dims [lane*4,+4).
// Each thread holds its 16 float4 row-chunks in regs across both passes.
// Upper warps shadow the softmax on tid&127 (identical values; stores guarded).
// Grid (320, 2).
// ---------------------------------------------------------------------------
__global__ __launch_bounds__(256) void attn_kernel(
    const int* __restrict__ mask_a, const int* __restrict__ mask_b,
    float* __restrict__ out)
{
    __shared__ __align__(16) float meanv[128];
    __shared__ __align__(16) float part[8][128];
    __shared__ float sc[128], wv[128], red[8];

    const int side = blockIdx.y;
    const int n    = blockIdx.x;
    const int b    = n / RV_NUM;
    const int tid  = threadIdx.x;
    const int lane = tid & 31, w = tid >> 5;     // w: 0..7
    const int tok  = tid & 127;                  // shadowed token index

    const float* __restrict__ T = g_t[side] + (size_t)n * RV_LEN * ND;
    const int*   __restrict__ mask = side ? mask_b : mask_a;

    if (tid < 128)
        meanv[tid] = g_mean[side ^ 1][b * ND + tid] * (1.0f / (float)MTOK);
    __syncthreads();

    const float4 mv = *(const float4*)&meanv[lane * 4];

    // Single read of the tile: 16 rows per warp, one float4 chunk per lane.
    float4 x[16];
    #pragma unroll
    for (int t = 0; t < 16; ++t)
        x[t] = *(const float4*)(T + (size_t)(w * 16 + t) * ND + lane * 4);

    // Pass 1: scores from registers.
    #pragma unroll
    for (int t = 0; t < 16; ++t) {
        float p = x[t].x * mv.x + x[t].y * mv.y + x[t].z * mv.z + x[t].w * mv.w;
        #pragma unroll
        for (int o = 16; o; o >>= 1) p += __shfl_xor_sync(0xffffffffu, p, o);
        if (lane == 0) sc[w * 16 + t] = p;
    }
    __syncthreads();

    // Masked softmax over 128 tokens (warps 4-7 shadow warps 0-3).
    float logit = (mask[n * RV_LEN + tok] > 0) ? sc[tok] : -1e9f;
    float v = logit;
    #pragma unroll
    for (int o = 16; o; o >>= 1) v = fmaxf(v, __shfl_xor_sync(0xffffffffu, v, o));
    if (lane == 0 && w < 4) red[w] = v;
    __syncthreads();
    const float gmax = fmaxf(fmaxf(red[0], red[1]), fmaxf(red[2], red[3]));

    const float e = __expf(logit - gmax);
    v = e;
    #pragma unroll
    for (int o = 16; o; o >>= 1) v += __shfl_xor_sync(0xffffffffu, v, o);
    if (lane == 0 && w < 4) red[4 + w] = v;
    __syncthreads();
    const float gsum = red[4] + red[5] + red[6] + red[7];

    const float wgt = e / gsum;
    if (tid < 128) {
        wv[tid] = wgt;
        out[(size_t)(2 + side) * ROWS + (size_t)n * RV_LEN + tid] = wgt;
    }
    __syncthreads();

    // Pass 2: weighted sum from the SAME registers (no second g_t read).
    float4 acc = make_float4(0.f, 0.f, 0.f, 0.f);
    #pragma unroll
    for (int t = 0; t < 16; ++t) {
        const float wl = wv[w * 16 + t];
        acc.x += wl * x[t].x; acc.y += wl * x[t].y;
        acc.z += wl * x[t].z; acc.w += wl * x[t].w;
    }
    *(float4*)&part[w][lane * 4] = acc;
    __syncthreads();
    if (tid < 128) {
        float s = part[0][tid] + part[1][tid] + part[2][tid] + part[3][tid]
                + part[4][tid] + part[5][tid] + part[6][tid] + part[7][tid];
        out[(size_t)side * ROWS + (size_t)n * ND + tid] = s;
    }
}

// ---------------------------------------------------------------------------
extern "C" void kernel_launch(void* const* d_in, const int* in_sizes, int n_in,
                              void* d_out, int out_size)
{
    const float* seq_a  = (const float*)d_in[0];
    const float* seq_b  = (const float*)d_in[1];
    const int*   mask_a = (const int*)d_in[2];
    const int*   mask_b = (const int*)d_in[3];
    const float* W      = (const float*)d_in[4];
    const float* bias   = (const float*)d_in[5];
    float* out = (float*)d_out;

    cudaFuncSetAttribute(gemm_mma_kernel, cudaFuncAttributeMaxDynamicSharedMemorySize, GEMM_SMEM);

    prep_w_kernel<<<160, 256>>>(W);

    dim3 g1(ROWS / BM, 2);
    gemm_mma_kernel<<<g1, 256, GEMM_SMEM>>>(seq_a, seq_b, bias);

    dim3 g3(NREV, 2);
    attn_kernel<<<g3, 256>>>(mask_a, mask_b, out);
}